// round 16
// baseline (speedup 1.0000x reference)
#include <cuda_runtime.h>
#include <cuda_fp16.h>
#include <cstdint>
#include <math.h>

// ---------------- problem sizes ----------------
#define BD   512
#define DD   2048
#define NTOT (BD*DD)
#define NV   (NTOT/4)      // 262144
#define WTOT (DD*DD)
#define WV   (WTOT/4)

#define MAX_STEPS 32
#define TOLC      0.01f
#define SPEED_TOL 1e-3f
#define DT0       0.1f
#define MIN_DT    0.1f

#define EW_BLK  256
#define EW_GRID (NV / EW_BLK)   // 1024

// ---------------- device state ----------------
__device__ float g_X [NTOT];        // x buffer 0
__device__ float g_X5[NTOT];        // x buffer 1
__device__ uint8_t g_SP[2][NTOT];   // stage-input parity bits ((int)xs & 1)
__device__ __half g_SA[2][NTOT];    // stage delta operand (fp16): r(XS_s) - r(x)
__device__ __half g_DX1[NTOT];      // step delta operand: r(x_new) - r(x_old)
__device__ __half g_A0[NTOT];       // fp16 r(x0) for the one-time full GEMM
__device__ float g_G1[NTOT];        // running base GEMM W @ r(x_cur)
__device__ __half g_Wh[WTOT];
__device__ __half g_Wl[WTOT];
__device__ float g_K [5][NTOT];     // K1..K5 (K6 never stored)
__device__ float g_dt;
__device__ int   g_done;
__device__ int   g_cur;
__device__ int   g_clean;           // 1: x unchanged since last stage-1 (rejected step)
__device__ unsigned int g_err_bits;
__device__ unsigned int g_spd_bits;
__device__ unsigned int g_cnt;
__device__ float*  g_pX;            // = current x buffer

// ---------------- helpers ----------------
__device__ __forceinline__ float reflect_f(float x) {
    int i = (int)x;
    return ((i & 1) == 0) ? x : 1.0f - x;
}
__device__ __forceinline__ uint32_t smem_u32(const void* p) {
    uint32_t a;
    asm("{ .reg .u64 t; cvta.to.shared.u64 t, %1; cvt.u32.u64 %0, t; }" : "=r"(a) : "l"(p));
    return a;
}
__device__ __forceinline__ void cp16(uint32_t dst, const void* src) {
    asm volatile("cp.async.cg.shared.global [%0], [%1], 16;" :: "r"(dst), "l"(src));
}
__device__ __forceinline__ void cp_commit() { asm volatile("cp.async.commit_group;" ::: "memory"); }
template <int N> __device__ __forceinline__ void cp_wait() {
    asm volatile("cp.async.wait_group %0;" :: "n"(N) : "memory");
}
__device__ __forceinline__ void ldsm4(uint32_t* r, uint32_t addr) {
    asm volatile("ldmatrix.sync.aligned.m8n8.x4.shared.b16 {%0,%1,%2,%3}, [%4];"
                 : "=r"(r[0]), "=r"(r[1]), "=r"(r[2]), "=r"(r[3]) : "r"(addr));
}
__device__ __forceinline__ void mma16816(float* c, const uint32_t* a, const uint32_t* b) {
    asm("mma.sync.aligned.m16n8k16.row.col.f32.f16.f16.f32 "
        "{%0,%1,%2,%3}, {%4,%5,%6,%7}, {%8,%9}, {%0,%1,%2,%3};"
        : "+f"(c[0]), "+f"(c[1]), "+f"(c[2]), "+f"(c[3])
        : "r"(a[0]), "r"(a[1]), "r"(a[2]), "r"(a[3]), "r"(b[0]), "r"(b[1]));
}

// ---------------- RKF coefficients ----------------
template <int S> struct RK {
    static constexpr float c1 = (S==1)?0.25f : (S==2)?(float)(3.0/32.0) : (S==3)?(float)(1932.0/2197.0)
                              : (S==4)?(float)(439.0/216.0) : (float)(-8.0/27.0);
    static constexpr float c2 = (S==2)?(float)(9.0/32.0) : (S==3)?(float)(-7200.0/2197.0)
                              : (S==4)?-8.0f : 2.0f;
    static constexpr float c3 = (S==3)?(float)(7296.0/2197.0) : (S==4)?(float)(3680.0/513.0)
                              : (float)(-3544.0/2565.0);
    static constexpr float c4 = (S==4)?(float)(-845.0/4104.0) : (float)(1859.0/4104.0);
    static constexpr float c5 = (float)(-11.0/40.0);
    static constexpr float cS = (S==1)?c1 : (S==2)?c2 : (S==3)?c3 : (S==4)?c4 : c5;
};

// ---------------- init / split ----------------
__global__ void k_splitW(const float* __restrict__ W) {
    int i = blockIdx.x * blockDim.x + threadIdx.x;
    float4 w = ((const float4*)W)[i];
    float v[4] = {w.x, w.y, w.z, w.w};
    __half h[4], l[4];
#pragma unroll
    for (int c = 0; c < 4; c++) {
        h[c] = __float2half_rn(v[c]);
        l[c] = __float2half_rn(v[c] - __half2float(h[c]));
    }
    *(uint2*)&g_Wh[i * 4] = *(uint2*)h;
    *(uint2*)&g_Wl[i * 4] = *(uint2*)l;
}

__global__ void k_init(const float* __restrict__ x0) {
    int i = blockIdx.x * blockDim.x + threadIdx.x;
    float4 x = ((const float4*)x0)[i];
    ((float4*)g_X)[i] = x;
    float v[4] = {x.x, x.y, x.z, x.w};
    __half h[4];
#pragma unroll
    for (int c = 0; c < 4; c++) h[c] = __float2half_rn(reflect_f(v[c]));
    *(uint2*)&g_A0[i * 4] = *(uint2*)h;
    if (i == 0) {
        g_dt = DT0; g_done = 0; g_cur = 0; g_clean = 0;
        g_err_bits = 0u; g_spd_bits = 0u; g_cnt = 0u;
        g_pX = g_X;
    }
}

// ================= one-time full GEMM (stage 1, step 0; launched ONCE) =================
#define BMT 128
#define BNT 64
#define PITCH 144
#define BH_OFF (128 * PITCH)
#define BL_OFF (128 * PITCH + 64 * PITCH)
#define STAGE  (128 * PITCH + 2 * 64 * PITCH)  // 36864
#define FULL_SMEM (4 * STAGE)                  // 147456
#define FNITER (DD / 64)                       // 32

__device__ __forceinline__ void load_stage_full(uint32_t sbase, int k0, int bm, int bn, int tid) {
#pragma unroll
    for (int i = 0; i < 2; i++) {
        int ch = tid + i * 512;
        int r = ch >> 3, c = ch & 7;
        uint32_t off = (uint32_t)(r * PITCH + c * 16);
        cp16(sbase + off, g_A0 + (size_t)(bm + r) * DD + k0 + c * 8);
    }
    {
        int r = tid >> 3, c = tid & 7;
        uint32_t off = (uint32_t)(r * PITCH + c * 16);
        size_t go = (size_t)(bn + r) * DD + k0 + c * 8;
        cp16(sbase + BH_OFF + off, g_Wh + go);
        cp16(sbase + BL_OFF + off, g_Wl + go);
    }
    cp_commit();
}

__global__ __launch_bounds__(512, 1)
void k_g1_full(const float* __restrict__ bias) {
    extern __shared__ char smem[];
    uint32_t sb = smem_u32(smem);
    const int tid  = threadIdx.x;
    const int wid  = tid >> 5;
    const int lane = tid & 31;
    const int wm   = wid >> 2;
    const int wn   = wid & 3;
    const int bm   = blockIdx.y * BMT;
    const int bn   = blockIdx.x * BNT;

    float acc[2][2][4];
#pragma unroll
    for (int mt = 0; mt < 2; mt++)
#pragma unroll
        for (int nt = 0; nt < 2; nt++)
#pragma unroll
            for (int c = 0; c < 4; c++) acc[mt][nt][c] = 0.0f;

    load_stage_full(sb + 0 * STAGE, 0, bm, bn, tid);
    load_stage_full(sb + 1 * STAGE, 64, bm, bn, tid);
    load_stage_full(sb + 2 * STAGE, 128, bm, bn, tid);

    const int g  = lane >> 3;
    const int l7 = lane & 7;
    const uint32_t offA0 = (uint32_t)((wm * 32 + ((g & 1) << 3) + l7) * PITCH + (g >> 1) * 16);
    const uint32_t offA1 = offA0 + 16 * PITCH;
    const uint32_t offB  = (uint32_t)((wn * 16 + ((g >> 1) << 3) + l7) * PITCH + (g & 1) * 16);

    for (int it = 0; it < FNITER; ++it) {
        if (it < FNITER - 2)       cp_wait<2>();
        else if (it == FNITER - 2) cp_wait<1>();
        else                       cp_wait<0>();
        __syncthreads();
        int J = it + 3;
        if (J < FNITER) load_stage_full(sb + (uint32_t)((J & 3) * STAGE), J * 64, bm, bn, tid);

        uint32_t stg = sb + (uint32_t)((it & 3) * STAGE);
#pragma unroll
        for (int ks = 0; ks < 4; ks++) {
            uint32_t koff = (uint32_t)(ks * 32);
            uint32_t a0[4], a1[4], bh[4], bl[4];
            ldsm4(a0, stg + offA0 + koff);
            ldsm4(a1, stg + offA1 + koff);
            ldsm4(bh, stg + BH_OFF + offB + koff);
            ldsm4(bl, stg + BL_OFF + offB + koff);
#pragma unroll
            for (int nt = 0; nt < 2; nt++) {
                mma16816(acc[0][nt], a0, &bh[nt * 2]);
                mma16816(acc[1][nt], a1, &bh[nt * 2]);
                mma16816(acc[0][nt], a0, &bl[nt * 2]);
                mma16816(acc[1][nt], a1, &bl[nt * 2]);
            }
        }
    }

    const float dt = DT0;
    const float* Xc = g_X;
#pragma unroll
    for (int mt = 0; mt < 2; mt++) {
        int m0 = bm + wm * 32 + mt * 16 + (lane >> 2);
#pragma unroll
        for (int nt = 0; nt < 2; nt++) {
            int n0 = bn + wn * 16 + nt * 8 + 2 * (lane & 3);
            float2 bv = *(const float2*)&bias[n0];
#pragma unroll
            for (int h = 0; h < 2; h++) {
                int m = m0 + h * 8;
                size_t idx = (size_t)m * DD + n0;
                float g0 = acc[mt][nt][h * 2 + 0];
                float g1v = acc[mt][nt][h * 2 + 1];
                *(float2*)&g_G1[idx] = make_float2(g0, g1v);
                float2 xc = *(const float2*)&Xc[idx];
                float v0 = g0 + bv.x, v1 = g1v + bv.y;
                float k0v = (((int)xc.x & 1) == 0) ? v0 : -v0;
                float k1v = (((int)xc.y & 1) == 0) ? v1 : -v1;
                *(float2*)&g_K[0][idx] = make_float2(k0v, k1v);
                float nx0 = xc.x + dt * 0.25f * k0v;
                float nx1 = xc.y + dt * 0.25f * k1v;
                uchar2 pp; pp.x = (uint8_t)((int)nx0 & 1); pp.y = (uint8_t)((int)nx1 & 1);
                *(uchar2*)&g_SP[0][idx] = pp;
                __half hh[2];
                hh[0] = __float2half_rn(reflect_f(nx0) - reflect_f(xc.x));
                hh[1] = __float2half_rn(reflect_f(nx1) - reflect_f(xc.y));
                *(uint32_t*)&g_SA[0][idx] = *(uint32_t*)hh;
            }
        }
    }
}

// ================= delta GEMMs (1-term, BKC=128, 3-deep, 1024 threads / 32 warps) ====
#define PITCH2 272
#define B2_OFF (128 * PITCH2)            // 34816
#define STAGE2 (192 * PITCH2)            // 52224
#define DELTA_SMEM (3 * STAGE2)          // 156672
#define NITER2 (DD / 128)                // 16
#define DTHREADS 1024

__device__ __forceinline__ void load_stage_d(uint32_t sbase, int k0, int bm, int bn, int tid,
                                             const __half* Ap) {
#pragma unroll
    for (int i = 0; i < 2; i++) {        // A: 2048 chunks (128 rows x 16)
        int ch = tid + i * 1024;
        int r = ch >> 4, c = ch & 15;
        cp16(sbase + (uint32_t)(r * PITCH2 + c * 16),
             Ap + (size_t)(bm + r) * DD + k0 + c * 8);
    }
    {                                    // B: 1024 chunks (64 rows x 16)
        int r = tid >> 4, c = tid & 15;
        cp16(sbase + B2_OFF + (uint32_t)(r * PITCH2 + c * 16),
             g_Wh + (size_t)(bn + r) * DD + k0 + c * 8);
    }
    cp_commit();
}

template <int S>
__global__ __launch_bounds__(DTHREADS, 1)
void k_gemm(const float* __restrict__ bias) {
    if (g_done) return;
    extern __shared__ char smem[];
    uint32_t sb = smem_u32(smem);
    const int tid  = threadIdx.x;
    const int wid  = tid >> 5;
    const int lane = tid & 31;
    const int wm   = wid >> 2;      // 0..7 -> 16 rows each
    const int wn   = wid & 3;       // 0..3 -> 16 cols each
    const int bm   = blockIdx.y * BMT;
    const int bn   = blockIdx.x * BNT;

    // Rejected previous step: x unchanged -> G1/K1 valid; just re-prep stage 2 (new dt).
    if (S == 1 && g_clean) {
        const float dt = g_dt;
        const float* Xc = g_pX;
        const float* K0 = g_K[0];
        for (int e = tid; e < BMT * BNT / 2; e += DTHREADS) {
            int r = e >> 5, c2 = (e & 31) * 2;
            size_t idx = (size_t)(bm + r) * DD + bn + c2;
            float2 xc = *(const float2*)&Xc[idx];
            float2 k  = *(const float2*)&K0[idx];
            float nx0 = xc.x + dt * 0.25f * k.x;
            float nx1 = xc.y + dt * 0.25f * k.y;
            uchar2 pp; pp.x = (uint8_t)((int)nx0 & 1); pp.y = (uint8_t)((int)nx1 & 1);
            *(uchar2*)&g_SP[0][idx] = pp;
            __half hh[2];
            hh[0] = __float2half_rn(reflect_f(nx0) - reflect_f(xc.x));
            hh[1] = __float2half_rn(reflect_f(nx1) - reflect_f(xc.y));
            *(uint32_t*)&g_SA[0][idx] = *(uint32_t*)hh;
        }
        return;
    }

    const __half* Ap = (S == 1) ? g_DX1 : g_SA[S & 1];

    float acc[2][4];                // [n8 tile][frag]
#pragma unroll
    for (int nt = 0; nt < 2; nt++)
#pragma unroll
        for (int c = 0; c < 4; c++) acc[nt][c] = 0.0f;

    load_stage_d(sb + 0 * STAGE2, 0, bm, bn, tid, Ap);
    load_stage_d(sb + 1 * STAGE2, 128, bm, bn, tid, Ap);

    const int g  = lane >> 3;
    const int l7 = lane & 7;
    const uint32_t offA = (uint32_t)((wm * 16 + ((g & 1) << 3) + l7) * PITCH2 + (g >> 1) * 16);
    const uint32_t offB = (uint32_t)((wn * 16 + ((g >> 1) << 3) + l7) * PITCH2 + (g & 1) * 16);

    uint32_t stg_idx = 0;
    for (int it = 0; it < NITER2; ++it) {
        if (it < NITER2 - 1) cp_wait<1>(); else cp_wait<0>();
        __syncthreads();
        int J = it + 2;
        if (J < NITER2) {
            int b = J % 3;
            load_stage_d(sb + (uint32_t)(b * STAGE2), J * 128, bm, bn, tid, Ap);
        }
        uint32_t stg = sb + stg_idx * STAGE2;
        stg_idx = (stg_idx == 2) ? 0 : stg_idx + 1;
#pragma unroll
        for (int ks = 0; ks < 8; ks++) {
            uint32_t koff = (uint32_t)(ks * 32);
            uint32_t a[4], bh[4];
            ldsm4(a, stg + offA + koff);
            ldsm4(bh, stg + B2_OFF + offB + koff);
            mma16816(acc[0], a, &bh[0]);
            mma16816(acc[1], a, &bh[2]);
        }
    }

    // ---- epilogue ----
    const float* Xc = g_pX;
    const float dt = g_dt;
    float emax = 0.0f, smax = 0.0f;
    const int cur = g_cur;
    float* DST = (S == 6) ? (cur ? g_X : g_X5) : (float*)0;

    const int m0 = bm + wm * 16 + (lane >> 2);
#pragma unroll
    for (int nt = 0; nt < 2; nt++) {
        int n0 = bn + wn * 16 + nt * 8 + 2 * (lane & 3);
        float2 bv = *(const float2*)&bias[n0];
#pragma unroll
        for (int h = 0; h < 2; h++) {
            int m = m0 + h * 8;
            size_t idx = (size_t)m * DD + n0;
            float a0v = acc[nt][h * 2 + 0];
            float a1v = acc[nt][h * 2 + 1];
            float2 gb = *(const float2*)&g_G1[idx];
            float g0 = gb.x + a0v, g1v = gb.y + a1v;
            if (S == 1) *(float2*)&g_G1[idx] = make_float2(g0, g1v);
            float v0 = g0 + bv.x, v1 = g1v + bv.y;
            float2 xc = *(const float2*)&Xc[idx];
            float k0v, k1v;
            if (S == 1) {
                k0v = (((int)xc.x & 1) == 0) ? v0 : -v0;
                k1v = (((int)xc.y & 1) == 0) ? v1 : -v1;
            } else {
                uchar2 pp = *(const uchar2*)&g_SP[S & 1][idx];
                k0v = pp.x ? -v0 : v0;
                k1v = pp.y ? -v1 : v1;
            }
            if (S < 6) {
                *(float2*)&g_K[S - 1][idx] = make_float2(k0v, k1v);
                float s0 = RK<S>::cS * k0v, s1 = RK<S>::cS * k1v;
                if (S >= 2) { float2 k = *(const float2*)&g_K[0][idx]; s0 += RK<S>::c1 * k.x; s1 += RK<S>::c1 * k.y; }
                if (S >= 3) { float2 k = *(const float2*)&g_K[1][idx]; s0 += RK<S>::c2 * k.x; s1 += RK<S>::c2 * k.y; }
                if (S >= 4) { float2 k = *(const float2*)&g_K[2][idx]; s0 += RK<S>::c3 * k.x; s1 += RK<S>::c3 * k.y; }
                if (S >= 5) { float2 k = *(const float2*)&g_K[3][idx]; s0 += RK<S>::c4 * k.x; s1 += RK<S>::c4 * k.y; }
                float nx0 = xc.x + dt * s0;
                float nx1 = xc.y + dt * s1;
                uchar2 pp2; pp2.x = (uint8_t)((int)nx0 & 1); pp2.y = (uint8_t)((int)nx1 & 1);
                *(uchar2*)&g_SP[(S + 1) & 1][idx] = pp2;
                __half hh[2];
                hh[0] = __float2half_rn(reflect_f(nx0) - reflect_f(xc.x));
                hh[1] = __float2half_rn(reflect_f(nx1) - reflect_f(xc.y));
                *(uint32_t*)&g_SA[(S + 1) & 1][idx] = *(uint32_t*)hh;
            } else {
                const float B1 = (float)(16.0 / 135.0),  B3 = (float)(6656.0 / 12825.0);
                const float B4 = (float)(28561.0 / 56430.0), B5f = (float)(-9.0 / 50.0), B6 = (float)(2.0 / 55.0);
                const float C1 = (float)(25.0 / 216.0),  C3 = (float)(1408.0 / 2565.0);
                const float C4 = (float)(2197.0 / 4104.0), C5 = (float)(-1.0 / 5.0);
                float2 k1 = *(const float2*)&g_K[0][idx];
                float2 k3 = *(const float2*)&g_K[2][idx];
                float2 k4 = *(const float2*)&g_K[3][idx];
                float2 k5 = *(const float2*)&g_K[4][idx];
                float s5_0 = B1 * k1.x + B3 * k3.x + B4 * k4.x + B5f * k5.x + B6 * k0v;
                float s5_1 = B1 * k1.y + B3 * k3.y + B4 * k4.y + B5f * k5.y + B6 * k1v;
                float s4_0 = C1 * k1.x + C3 * k3.x + C4 * k4.x + C5 * k5.x;
                float s4_1 = C1 * k1.y + C3 * k3.y + C4 * k4.y + C5 * k5.y;
                float x5_0 = xc.x + dt * s5_0;
                float x5_1 = xc.y + dt * s5_1;
                float x4_0 = xc.x + dt * s4_0;
                float x4_1 = xc.y + dt * s4_1;
                emax = fmaxf(emax, fmaxf(fabsf(x5_0 - x4_0), fabsf(x5_1 - x4_1)));
                smax = fmaxf(smax, fmaxf(fabsf(x5_0 - xc.x), fabsf(x5_1 - xc.y)));
                *(float2*)&DST[idx] = make_float2(x5_0, x5_1);
                __half dh[2];
                dh[0] = __float2half_rn(reflect_f(x5_0) - reflect_f(xc.x));
                dh[1] = __float2half_rn(reflect_f(x5_1) - reflect_f(xc.y));
                *(uint32_t*)&g_DX1[idx] = *(uint32_t*)dh;
            }
        }
    }

    if (S == 6) {
#pragma unroll
        for (int off = 16; off > 0; off >>= 1) {
            emax = fmaxf(emax, __shfl_xor_sync(0xffffffffu, emax, off));
            smax = fmaxf(smax, __shfl_xor_sync(0xffffffffu, smax, off));
        }
        if (lane == 0) {
            atomicMax(&g_err_bits, __float_as_uint(emax));
            atomicMax(&g_spd_bits, __float_as_uint(smax));
        }
        __syncthreads();
        if (tid == 0) {
            __threadfence();
            unsigned int old = atomicAdd(&g_cnt, 1u);
            if (old == gridDim.x * gridDim.y - 1) {
                float err = __uint_as_float(atomicMax(&g_err_bits, 0u));
                float spd = __uint_as_float(atomicMax(&g_spd_bits, 0u));
                float dtc = g_dt;
                int accept = (err < TOLC) ? 1 : 0;
                int ncur = g_cur;
                if (accept) {
                    ncur ^= 1;
                    g_cur = ncur;
                    if ((spd / dtc) < SPEED_TOL) g_done = 1;
                }
                g_clean = accept ? 0 : 1;
                g_pX = ncur ? g_X5 : g_X;
                float scale = 0.9f * powf(TOLC / (err + 1e-12f), 0.2f);
                scale = fminf(fmaxf(scale, 0.1f), 4.0f);
                g_dt = fmaxf(dtc * scale, MIN_DT);
                g_err_bits = 0u; g_spd_bits = 0u; g_cnt = 0u;
            }
        }
    }
}

// ---------------- output ----------------
__global__ void k_final(float* __restrict__ out) {
    const float4* SRC = (const float4*)(g_cur ? g_X5 : g_X);
    int i = blockIdx.x * blockDim.x + threadIdx.x;
    ((float4*)out)[i] = SRC[i];
}

// ---------------- launch ----------------
extern "C" void kernel_launch(void* const* d_in, const int* in_sizes, int n_in,
                              void* d_out, int out_size) {
    const float* x0   = (const float*)d_in[0];
    const float* W    = (const float*)d_in[1];
    const float* bias = (const float*)d_in[2];
    float* out = (float*)d_out;

    cudaFuncSetAttribute(k_g1_full, cudaFuncAttributeMaxDynamicSharedMemorySize, FULL_SMEM);
    cudaFuncSetAttribute(k_gemm<1>, cudaFuncAttributeMaxDynamicSharedMemorySize, DELTA_SMEM);
    cudaFuncSetAttribute(k_gemm<2>, cudaFuncAttributeMaxDynamicSharedMemorySize, DELTA_SMEM);
    cudaFuncSetAttribute(k_gemm<3>, cudaFuncAttributeMaxDynamicSharedMemorySize, DELTA_SMEM);
    cudaFuncSetAttribute(k_gemm<4>, cudaFuncAttributeMaxDynamicSharedMemorySize, DELTA_SMEM);
    cudaFuncSetAttribute(k_gemm<5>, cudaFuncAttributeMaxDynamicSharedMemorySize, DELTA_SMEM);
    cudaFuncSetAttribute(k_gemm<6>, cudaFuncAttributeMaxDynamicSharedMemorySize, DELTA_SMEM);

    dim3 ggrid(DD / BNT, BD / BMT);  // (32, 4) = 128 CTAs

    k_splitW<<<WV / EW_BLK, EW_BLK>>>(W);
    k_init<<<EW_GRID, EW_BLK>>>(x0);
    k_g1_full<<<ggrid, 512, FULL_SMEM>>>(bias);    // once: stage 1 of step 0

    // step 0: stage 1 already done by k_g1_full
    k_gemm<2><<<ggrid, DTHREADS, DELTA_SMEM>>>(bias);
    k_gemm<3><<<ggrid, DTHREADS, DELTA_SMEM>>>(bias);
    k_gemm<4><<<ggrid, DTHREADS, DELTA_SMEM>>>(bias);
    k_gemm<5><<<ggrid, DTHREADS, DELTA_SMEM>>>(bias);
    k_gemm<6><<<ggrid, DTHREADS, DELTA_SMEM>>>(bias);

    for (int step = 1; step < MAX_STEPS; step++) {
        k_gemm<1><<<ggrid, DTHREADS, DELTA_SMEM>>>(bias);
        k_gemm<2><<<ggrid, DTHREADS, DELTA_SMEM>>>(bias);
        k_gemm<3><<<ggrid, DTHREADS, DELTA_SMEM>>>(bias);
        k_gemm<4><<<ggrid, DTHREADS, DELTA_SMEM>>>(bias);
        k_gemm<5><<<ggrid, DTHREADS, DELTA_SMEM>>>(bias);
        k_gemm<6><<<ggrid, DTHREADS, DELTA_SMEM>>>(bias);   // fused combine + decide
    }

    k_final<<<EW_GRID, EW_BLK>>>(out);
}

// round 17
// speedup vs baseline: 1.1435x; 1.1435x over previous
#include <cuda_runtime.h>
#include <cuda_fp16.h>
#include <cstdint>
#include <math.h>

// ---------------- problem sizes ----------------
#define BD   512
#define DD   2048
#define NTOT (BD*DD)
#define NV   (NTOT/4)      // 262144
#define WTOT (DD*DD)
#define WV   (WTOT/4)

#define MAX_STEPS 32
#define TOLC      0.01f
#define SPEED_TOL 1e-3f
#define DT0       0.1f
#define MIN_DT    0.1f

#define EW_BLK  256
#define EW_GRID (NV / EW_BLK)   // 1024

// ---------------- device state ----------------
__device__ float g_X [NTOT];        // x buffer 0
__device__ float g_X5[NTOT];        // x buffer 1
__device__ uint8_t g_SP[2][NTOT];   // stage-input parity bits ((int)xs & 1)
__device__ __half g_SA[2][NTOT];    // stage delta operand (fp16): r(XS_s) - r(x)
__device__ __half g_DX1[NTOT];      // step delta operand: r(x_new) - r(x_old)
__device__ __half g_A0[NTOT];       // fp16 r(x0) for the one-time full GEMM
__device__ float g_G1[NTOT];        // running base GEMM W @ r(x_cur)
__device__ __half g_Wh[WTOT];
__device__ __half g_Wl[WTOT];
__device__ float g_K [5][NTOT];     // K1..K5 (K6 never stored)
__device__ float g_dt;
__device__ int   g_done;
__device__ int   g_cur;
__device__ int   g_clean;           // 1: x unchanged since last stage-1 (rejected step)
__device__ unsigned int g_err_bits;
__device__ unsigned int g_spd_bits;
__device__ unsigned int g_cnt;
__device__ float*  g_pX;            // = current x buffer

// ---------------- helpers ----------------
__device__ __forceinline__ float reflect_f(float x) {
    int i = (int)x;
    return ((i & 1) == 0) ? x : 1.0f - x;
}
__device__ __forceinline__ uint32_t smem_u32(const void* p) {
    uint32_t a;
    asm("{ .reg .u64 t; cvta.to.shared.u64 t, %1; cvt.u32.u64 %0, t; }" : "=r"(a) : "l"(p));
    return a;
}
__device__ __forceinline__ void cp16(uint32_t dst, const void* src) {
    asm volatile("cp.async.cg.shared.global [%0], [%1], 16;" :: "r"(dst), "l"(src));
}
__device__ __forceinline__ void cp_commit() { asm volatile("cp.async.commit_group;" ::: "memory"); }
template <int N> __device__ __forceinline__ void cp_wait() {
    asm volatile("cp.async.wait_group %0;" :: "n"(N) : "memory");
}
__device__ __forceinline__ void ldsm4(uint32_t* r, uint32_t addr) {
    asm volatile("ldmatrix.sync.aligned.m8n8.x4.shared.b16 {%0,%1,%2,%3}, [%4];"
                 : "=r"(r[0]), "=r"(r[1]), "=r"(r[2]), "=r"(r[3]) : "r"(addr));
}
__device__ __forceinline__ void mma16816(float* c, const uint32_t* a, const uint32_t* b) {
    asm("mma.sync.aligned.m16n8k16.row.col.f32.f16.f16.f32 "
        "{%0,%1,%2,%3}, {%4,%5,%6,%7}, {%8,%9}, {%0,%1,%2,%3};"
        : "+f"(c[0]), "+f"(c[1]), "+f"(c[2]), "+f"(c[3])
        : "r"(a[0]), "r"(a[1]), "r"(a[2]), "r"(a[3]), "r"(b[0]), "r"(b[1]));
}

// ---------------- RKF coefficients ----------------
template <int S> struct RK {
    static constexpr float c1 = (S==1)?0.25f : (S==2)?(float)(3.0/32.0) : (S==3)?(float)(1932.0/2197.0)
                              : (S==4)?(float)(439.0/216.0) : (float)(-8.0/27.0);
    static constexpr float c2 = (S==2)?(float)(9.0/32.0) : (S==3)?(float)(-7200.0/2197.0)
                              : (S==4)?-8.0f : 2.0f;
    static constexpr float c3 = (S==3)?(float)(7296.0/2197.0) : (S==4)?(float)(3680.0/513.0)
                              : (float)(-3544.0/2565.0);
    static constexpr float c4 = (S==4)?(float)(-845.0/4104.0) : (float)(1859.0/4104.0);
    static constexpr float c5 = (float)(-11.0/40.0);
    static constexpr float cS = (S==1)?c1 : (S==2)?c2 : (S==3)?c3 : (S==4)?c4 : c5;
};

// ---------------- init / split ----------------
__global__ void k_splitW(const float* __restrict__ W) {
    int i = blockIdx.x * blockDim.x + threadIdx.x;
    float4 w = ((const float4*)W)[i];
    float v[4] = {w.x, w.y, w.z, w.w};
    __half h[4], l[4];
#pragma unroll
    for (int c = 0; c < 4; c++) {
        h[c] = __float2half_rn(v[c]);
        l[c] = __float2half_rn(v[c] - __half2float(h[c]));
    }
    *(uint2*)&g_Wh[i * 4] = *(uint2*)h;
    *(uint2*)&g_Wl[i * 4] = *(uint2*)l;
}

__global__ void k_init(const float* __restrict__ x0) {
    int i = blockIdx.x * blockDim.x + threadIdx.x;
    float4 x = ((const float4*)x0)[i];
    ((float4*)g_X)[i] = x;
    float v[4] = {x.x, x.y, x.z, x.w};
    __half h[4];
#pragma unroll
    for (int c = 0; c < 4; c++) h[c] = __float2half_rn(reflect_f(v[c]));
    *(uint2*)&g_A0[i * 4] = *(uint2*)h;
    if (i == 0) {
        g_dt = DT0; g_done = 0; g_cur = 0; g_clean = 0;
        g_err_bits = 0u; g_spd_bits = 0u; g_cnt = 0u;
        g_pX = g_X;
    }
}

// ================= one-time full GEMM (stage 1, step 0; launched ONCE) =================
#define BMT 128
#define BNT 64
#define PITCH 144
#define BH_OFF (128 * PITCH)
#define BL_OFF (128 * PITCH + 64 * PITCH)
#define STAGE  (128 * PITCH + 2 * 64 * PITCH)  // 36864
#define FULL_SMEM (4 * STAGE)                  // 147456
#define FNITER (DD / 64)                       // 32

__device__ __forceinline__ void load_stage_full(uint32_t sbase, int k0, int bm, int bn, int tid) {
#pragma unroll
    for (int i = 0; i < 2; i++) {
        int ch = tid + i * 512;
        int r = ch >> 3, c = ch & 7;
        uint32_t off = (uint32_t)(r * PITCH + c * 16);
        cp16(sbase + off, g_A0 + (size_t)(bm + r) * DD + k0 + c * 8);
    }
    {
        int r = tid >> 3, c = tid & 7;
        uint32_t off = (uint32_t)(r * PITCH + c * 16);
        size_t go = (size_t)(bn + r) * DD + k0 + c * 8;
        cp16(sbase + BH_OFF + off, g_Wh + go);
        cp16(sbase + BL_OFF + off, g_Wl + go);
    }
    cp_commit();
}

__global__ __launch_bounds__(512, 1)
void k_g1_full(const float* __restrict__ bias) {
    extern __shared__ char smem[];
    uint32_t sb = smem_u32(smem);
    const int tid  = threadIdx.x;
    const int wid  = tid >> 5;
    const int lane = tid & 31;
    const int wm   = wid >> 2;
    const int wn   = wid & 3;
    const int bm   = blockIdx.y * BMT;
    const int bn   = blockIdx.x * BNT;

    float acc[2][2][4];
#pragma unroll
    for (int mt = 0; mt < 2; mt++)
#pragma unroll
        for (int nt = 0; nt < 2; nt++)
#pragma unroll
            for (int c = 0; c < 4; c++) acc[mt][nt][c] = 0.0f;

    load_stage_full(sb + 0 * STAGE, 0, bm, bn, tid);
    load_stage_full(sb + 1 * STAGE, 64, bm, bn, tid);
    load_stage_full(sb + 2 * STAGE, 128, bm, bn, tid);

    const int g  = lane >> 3;
    const int l7 = lane & 7;
    const uint32_t offA0 = (uint32_t)((wm * 32 + ((g & 1) << 3) + l7) * PITCH + (g >> 1) * 16);
    const uint32_t offA1 = offA0 + 16 * PITCH;
    const uint32_t offB  = (uint32_t)((wn * 16 + ((g >> 1) << 3) + l7) * PITCH + (g & 1) * 16);

    for (int it = 0; it < FNITER; ++it) {
        if (it < FNITER - 2)       cp_wait<2>();
        else if (it == FNITER - 2) cp_wait<1>();
        else                       cp_wait<0>();
        __syncthreads();
        int J = it + 3;
        if (J < FNITER) load_stage_full(sb + (uint32_t)((J & 3) * STAGE), J * 64, bm, bn, tid);

        uint32_t stg = sb + (uint32_t)((it & 3) * STAGE);
#pragma unroll
        for (int ks = 0; ks < 4; ks++) {
            uint32_t koff = (uint32_t)(ks * 32);
            uint32_t a0[4], a1[4], bh[4], bl[4];
            ldsm4(a0, stg + offA0 + koff);
            ldsm4(a1, stg + offA1 + koff);
            ldsm4(bh, stg + BH_OFF + offB + koff);
            ldsm4(bl, stg + BL_OFF + offB + koff);
#pragma unroll
            for (int nt = 0; nt < 2; nt++) {
                mma16816(acc[0][nt], a0, &bh[nt * 2]);
                mma16816(acc[1][nt], a1, &bh[nt * 2]);
                mma16816(acc[0][nt], a0, &bl[nt * 2]);
                mma16816(acc[1][nt], a1, &bl[nt * 2]);
            }
        }
    }

    const float dt = DT0;
    const float* Xc = g_X;
#pragma unroll
    for (int mt = 0; mt < 2; mt++) {
        int m0 = bm + wm * 32 + mt * 16 + (lane >> 2);
#pragma unroll
        for (int nt = 0; nt < 2; nt++) {
            int n0 = bn + wn * 16 + nt * 8 + 2 * (lane & 3);
            float2 bv = *(const float2*)&bias[n0];
#pragma unroll
            for (int h = 0; h < 2; h++) {
                int m = m0 + h * 8;
                size_t idx = (size_t)m * DD + n0;
                float g0 = acc[mt][nt][h * 2 + 0];
                float g1v = acc[mt][nt][h * 2 + 1];
                *(float2*)&g_G1[idx] = make_float2(g0, g1v);
                float2 xc = *(const float2*)&Xc[idx];
                float v0 = g0 + bv.x, v1 = g1v + bv.y;
                float k0v = (((int)xc.x & 1) == 0) ? v0 : -v0;
                float k1v = (((int)xc.y & 1) == 0) ? v1 : -v1;
                *(float2*)&g_K[0][idx] = make_float2(k0v, k1v);
                float nx0 = xc.x + dt * 0.25f * k0v;
                float nx1 = xc.y + dt * 0.25f * k1v;
                uchar2 pp; pp.x = (uint8_t)((int)nx0 & 1); pp.y = (uint8_t)((int)nx1 & 1);
                *(uchar2*)&g_SP[0][idx] = pp;
                __half hh[2];
                hh[0] = __float2half_rn(reflect_f(nx0) - reflect_f(xc.x));
                hh[1] = __float2half_rn(reflect_f(nx1) - reflect_f(xc.y));
                *(uint32_t*)&g_SA[0][idx] = *(uint32_t*)hh;
            }
        }
    }
}

// ================= delta GEMMs (1-term, BKC=128, 3-deep, 512 thr, 8x(32x32) x 2 kg) ==
#define PITCH2 272
#define B2_OFF (128 * PITCH2)            // 34816
#define STAGE2 (192 * PITCH2)            // 52224
#define DELTA_SMEM (3 * STAGE2)          // 156672
#define NITER2 (DD / 128)                // 16

__device__ __forceinline__ void load_stage_d(uint32_t sbase, int k0, int bm, int bn, int tid,
                                             const __half* Ap) {
#pragma unroll
    for (int i = 0; i < 4; i++) {
        int ch = tid + i * 512;
        int r = ch >> 4, c = ch & 15;
        cp16(sbase + (uint32_t)(r * PITCH2 + c * 16),
             Ap + (size_t)(bm + r) * DD + k0 + c * 8);
    }
#pragma unroll
    for (int i = 0; i < 2; i++) {
        int ch = tid + i * 512;
        int r = ch >> 4, c = ch & 15;
        cp16(sbase + B2_OFF + (uint32_t)(r * PITCH2 + c * 16),
             g_Wh + (size_t)(bn + r) * DD + k0 + c * 8);
    }
    cp_commit();
}

template <int S>
__global__ __launch_bounds__(512, 1)
void k_gemm(const float* __restrict__ bias) {
    if (g_done) return;
    extern __shared__ char smem[];
    uint32_t sb = smem_u32(smem);
    const int tid  = threadIdx.x;
    const int wid  = tid >> 5;
    const int lane = tid & 31;
    const int kg   = wid & 1;       // k-group (handles k16 slices of matching parity)
    const int ws   = wid >> 1;      // spatial warp 0..7
    const int wm   = ws >> 1;       // 0..3 -> 32 rows each
    const int wn   = ws & 1;        // 0..1 -> 32 cols each
    const int bm   = blockIdx.y * BMT;
    const int bn   = blockIdx.x * BNT;

    // Rejected previous step: x unchanged -> G1/K1 valid; just re-prep stage 2 (new dt).
    if (S == 1 && g_clean) {
        const float dt = g_dt;
        const float* Xc = g_pX;
        const float* K0 = g_K[0];
        for (int e = tid; e < BMT * BNT / 2; e += 512) {
            int r = e >> 5, c2 = (e & 31) * 2;
            size_t idx = (size_t)(bm + r) * DD + bn + c2;
            float2 xc = *(const float2*)&Xc[idx];
            float2 k  = *(const float2*)&K0[idx];
            float nx0 = xc.x + dt * 0.25f * k.x;
            float nx1 = xc.y + dt * 0.25f * k.y;
            uchar2 pp; pp.x = (uint8_t)((int)nx0 & 1); pp.y = (uint8_t)((int)nx1 & 1);
            *(uchar2*)&g_SP[0][idx] = pp;
            __half hh[2];
            hh[0] = __float2half_rn(reflect_f(nx0) - reflect_f(xc.x));
            hh[1] = __float2half_rn(reflect_f(nx1) - reflect_f(xc.y));
            *(uint32_t*)&g_SA[0][idx] = *(uint32_t*)hh;
        }
        return;
    }

    const __half* Ap = (S == 1) ? g_DX1 : g_SA[S & 1];

    float acc[2][4][4];             // [m16 tile][n8 tile][frag], warp tile 32x32
#pragma unroll
    for (int mt = 0; mt < 2; mt++)
#pragma unroll
        for (int nt = 0; nt < 4; nt++)
#pragma unroll
            for (int c = 0; c < 4; c++) acc[mt][nt][c] = 0.0f;

    load_stage_d(sb + 0 * STAGE2, 0, bm, bn, tid, Ap);
    load_stage_d(sb + 1 * STAGE2, 128, bm, bn, tid, Ap);

    const int g  = lane >> 3;
    const int l7 = lane & 7;
    const uint32_t offA0 = (uint32_t)((wm * 32 + ((g & 1) << 3) + l7) * PITCH2 + (g >> 1) * 16);
    const uint32_t offA1 = offA0 + 16 * PITCH2;
    const uint32_t offB0 = (uint32_t)((wn * 32 + ((g >> 1) << 3) + l7) * PITCH2 + (g & 1) * 16);
    const uint32_t offB1 = offB0 + 16 * PITCH2;
    const uint32_t kg32  = (uint32_t)(kg * 32);

    uint32_t stg_idx = 0;
    for (int it = 0; it < NITER2; ++it) {
        if (it < NITER2 - 1) cp_wait<1>(); else cp_wait<0>();
        __syncthreads();
        int J = it + 2;
        if (J < NITER2) {
            int b = J % 3;
            load_stage_d(sb + (uint32_t)(b * STAGE2), J * 128, bm, bn, tid, Ap);
        }
        uint32_t stg = sb + stg_idx * STAGE2;
        stg_idx = (stg_idx == 2) ? 0 : stg_idx + 1;
#pragma unroll
        for (int t = 0; t < 4; t++) {         // this warp's 4 k16 slices
            uint32_t koff = (uint32_t)(t * 64) + kg32;
            uint32_t a0[4], a1[4], bh0[4], bh1[4];
            ldsm4(a0,  stg + offA0 + koff);
            ldsm4(a1,  stg + offA1 + koff);
            ldsm4(bh0, stg + B2_OFF + offB0 + koff);
            ldsm4(bh1, stg + B2_OFF + offB1 + koff);
            mma16816(acc[0][0], a0, &bh0[0]);
            mma16816(acc[0][1], a0, &bh0[2]);
            mma16816(acc[0][2], a0, &bh1[0]);
            mma16816(acc[0][3], a0, &bh1[2]);
            mma16816(acc[1][0], a1, &bh0[0]);
            mma16816(acc[1][1], a1, &bh0[2]);
            mma16816(acc[1][2], a1, &bh1[0]);
            mma16816(acc[1][3], a1, &bh1[2]);
        }
    }

    // ---- 2-way k-group reduction; then split n-halves between the pair ----
    __syncthreads();
    float* red = (float*)smem;      // 8 ws * 1024 floats = 32KB (tiles no longer needed)
    if (kg == 1) {
#pragma unroll
        for (int mt = 0; mt < 2; mt++)
#pragma unroll
            for (int nt = 0; nt < 4; nt++)
#pragma unroll
                for (int c = 0; c < 4; c++)
                    red[ws * 1024 + ((mt * 4 + nt) * 4 + c) * 32 + lane] = acc[mt][nt][c];
    }
    __syncthreads();
    if (kg == 0) {
#pragma unroll
        for (int mt = 0; mt < 2; mt++)
#pragma unroll
            for (int nt = 0; nt < 4; nt++)
#pragma unroll
                for (int c = 0; c < 4; c++)
                    acc[mt][nt][c] += red[ws * 1024 + ((mt * 4 + nt) * 4 + c) * 32 + lane];
    }
    __syncthreads();
    if (kg == 0) {                  // hand n-tiles 2,3 to the kg=1 partner
#pragma unroll
        for (int mt = 0; mt < 2; mt++)
#pragma unroll
            for (int j = 0; j < 2; j++)
#pragma unroll
                for (int c = 0; c < 4; c++)
                    red[ws * 512 + ((mt * 2 + j) * 4 + c) * 32 + lane] = acc[mt][2 + j][c];
    }
    __syncthreads();
    float facc[2][2][4];            // each warp's final m32 x n16 slice
    if (kg == 0) {
#pragma unroll
        for (int mt = 0; mt < 2; mt++)
#pragma unroll
            for (int j = 0; j < 2; j++)
#pragma unroll
                for (int c = 0; c < 4; c++) facc[mt][j][c] = acc[mt][j][c];
    } else {
#pragma unroll
        for (int mt = 0; mt < 2; mt++)
#pragma unroll
            for (int j = 0; j < 2; j++)
#pragma unroll
                for (int c = 0; c < 4; c++)
                    facc[mt][j][c] = red[ws * 512 + ((mt * 2 + j) * 4 + c) * 32 + lane];
    }

    // ---- epilogue (each warp: m32 x n16) ----
    const float* Xc = g_pX;
    const float dt = g_dt;
    float emax = 0.0f, smax = 0.0f;
    const int cur = g_cur;
    float* DST = (S == 6) ? (cur ? g_X : g_X5) : (float*)0;

#pragma unroll
    for (int mt = 0; mt < 2; mt++) {
        int m0 = bm + wm * 32 + mt * 16 + (lane >> 2);
#pragma unroll
        for (int j = 0; j < 2; j++) {
            int n0 = bn + wn * 32 + kg * 16 + j * 8 + 2 * (lane & 3);
            float2 bv = *(const float2*)&bias[n0];
#pragma unroll
            for (int h = 0; h < 2; h++) {
                int m = m0 + h * 8;
                size_t idx = (size_t)m * DD + n0;
                float a0v = facc[mt][j][h * 2 + 0];
                float a1v = facc[mt][j][h * 2 + 1];
                float2 gb = *(const float2*)&g_G1[idx];
                float g0 = gb.x + a0v, g1v = gb.y + a1v;
                if (S == 1) *(float2*)&g_G1[idx] = make_float2(g0, g1v);
                float v0 = g0 + bv.x, v1 = g1v + bv.y;
                float2 xc = *(const float2*)&Xc[idx];
                float k0v, k1v;
                if (S == 1) {
                    k0v = (((int)xc.x & 1) == 0) ? v0 : -v0;
                    k1v = (((int)xc.y & 1) == 0) ? v1 : -v1;
                } else {
                    uchar2 pp = *(const uchar2*)&g_SP[S & 1][idx];
                    k0v = pp.x ? -v0 : v0;
                    k1v = pp.y ? -v1 : v1;
                }
                if (S < 6) {
                    *(float2*)&g_K[S - 1][idx] = make_float2(k0v, k1v);
                    float s0 = RK<S>::cS * k0v, s1 = RK<S>::cS * k1v;
                    if (S >= 2) { float2 k = *(const float2*)&g_K[0][idx]; s0 += RK<S>::c1 * k.x; s1 += RK<S>::c1 * k.y; }
                    if (S >= 3) { float2 k = *(const float2*)&g_K[1][idx]; s0 += RK<S>::c2 * k.x; s1 += RK<S>::c2 * k.y; }
                    if (S >= 4) { float2 k = *(const float2*)&g_K[2][idx]; s0 += RK<S>::c3 * k.x; s1 += RK<S>::c3 * k.y; }
                    if (S >= 5) { float2 k = *(const float2*)&g_K[3][idx]; s0 += RK<S>::c4 * k.x; s1 += RK<S>::c4 * k.y; }
                    float nx0 = xc.x + dt * s0;
                    float nx1 = xc.y + dt * s1;
                    uchar2 pp2; pp2.x = (uint8_t)((int)nx0 & 1); pp2.y = (uint8_t)((int)nx1 & 1);
                    *(uchar2*)&g_SP[(S + 1) & 1][idx] = pp2;
                    __half hh[2];
                    hh[0] = __float2half_rn(reflect_f(nx0) - reflect_f(xc.x));
                    hh[1] = __float2half_rn(reflect_f(nx1) - reflect_f(xc.y));
                    *(uint32_t*)&g_SA[(S + 1) & 1][idx] = *(uint32_t*)hh;
                } else {
                    const float B1 = (float)(16.0 / 135.0),  B3 = (float)(6656.0 / 12825.0);
                    const float B4 = (float)(28561.0 / 56430.0), B5f = (float)(-9.0 / 50.0), B6 = (float)(2.0 / 55.0);
                    const float C1 = (float)(25.0 / 216.0),  C3 = (float)(1408.0 / 2565.0);
                    const float C4 = (float)(2197.0 / 4104.0), C5 = (float)(-1.0 / 5.0);
                    float2 k1 = *(const float2*)&g_K[0][idx];
                    float2 k3 = *(const float2*)&g_K[2][idx];
                    float2 k4 = *(const float2*)&g_K[3][idx];
                    float2 k5 = *(const float2*)&g_K[4][idx];
                    float s5_0 = B1 * k1.x + B3 * k3.x + B4 * k4.x + B5f * k5.x + B6 * k0v;
                    float s5_1 = B1 * k1.y + B3 * k3.y + B4 * k4.y + B5f * k5.y + B6 * k1v;
                    float s4_0 = C1 * k1.x + C3 * k3.x + C4 * k4.x + C5 * k5.x;
                    float s4_1 = C1 * k1.y + C3 * k3.y + C4 * k4.y + C5 * k5.y;
                    float x5_0 = xc.x + dt * s5_0;
                    float x5_1 = xc.y + dt * s5_1;
                    float x4_0 = xc.x + dt * s4_0;
                    float x4_1 = xc.y + dt * s4_1;
                    emax = fmaxf(emax, fmaxf(fabsf(x5_0 - x4_0), fabsf(x5_1 - x4_1)));
                    smax = fmaxf(smax, fmaxf(fabsf(x5_0 - xc.x), fabsf(x5_1 - xc.y)));
                    *(float2*)&DST[idx] = make_float2(x5_0, x5_1);
                    __half dh[2];
                    dh[0] = __float2half_rn(reflect_f(x5_0) - reflect_f(xc.x));
                    dh[1] = __float2half_rn(reflect_f(x5_1) - reflect_f(xc.y));
                    *(uint32_t*)&g_DX1[idx] = *(uint32_t*)dh;
                }
            }
        }
    }

    if (S == 6) {
#pragma unroll
        for (int off = 16; off > 0; off >>= 1) {
            emax = fmaxf(emax, __shfl_xor_sync(0xffffffffu, emax, off));
            smax = fmaxf(smax, __shfl_xor_sync(0xffffffffu, smax, off));
        }
        if (lane == 0) {
            atomicMax(&g_err_bits, __float_as_uint(emax));
            atomicMax(&g_spd_bits, __float_as_uint(smax));
        }
        __syncthreads();
        if (tid == 0) {
            __threadfence();
            unsigned int old = atomicAdd(&g_cnt, 1u);
            if (old == gridDim.x * gridDim.y - 1) {
                float err = __uint_as_float(atomicMax(&g_err_bits, 0u));
                float spd = __uint_as_float(atomicMax(&g_spd_bits, 0u));
                float dtc = g_dt;
                int accept = (err < TOLC) ? 1 : 0;
                int ncur = g_cur;
                if (accept) {
                    ncur ^= 1;
                    g_cur = ncur;
                    if ((spd / dtc) < SPEED_TOL) g_done = 1;
                }
                g_clean = accept ? 0 : 1;
                g_pX = ncur ? g_X5 : g_X;
                float scale = 0.9f * powf(TOLC / (err + 1e-12f), 0.2f);
                scale = fminf(fmaxf(scale, 0.1f), 4.0f);
                g_dt = fmaxf(dtc * scale, MIN_DT);
                g_err_bits = 0u; g_spd_bits = 0u; g_cnt = 0u;
            }
        }
    }
}

// ---------------- output ----------------
__global__ void k_final(float* __restrict__ out) {
    const float4* SRC = (const float4*)(g_cur ? g_X5 : g_X);
    int i = blockIdx.x * blockDim.x + threadIdx.x;
    ((float4*)out)[i] = SRC[i];
}

// ---------------- launch ----------------
extern "C" void kernel_launch(void* const* d_in, const int* in_sizes, int n_in,
                              void* d_out, int out_size) {
    const float* x0   = (const float*)d_in[0];
    const float* W    = (const float*)d_in[1];
    const float* bias = (const float*)d_in[2];
    float* out = (float*)d_out;

    cudaFuncSetAttribute(k_g1_full, cudaFuncAttributeMaxDynamicSharedMemorySize, FULL_SMEM);
    cudaFuncSetAttribute(k_gemm<1>, cudaFuncAttributeMaxDynamicSharedMemorySize, DELTA_SMEM);
    cudaFuncSetAttribute(k_gemm<2>, cudaFuncAttributeMaxDynamicSharedMemorySize, DELTA_SMEM);
    cudaFuncSetAttribute(k_gemm<3>, cudaFuncAttributeMaxDynamicSharedMemorySize, DELTA_SMEM);
    cudaFuncSetAttribute(k_gemm<4>, cudaFuncAttributeMaxDynamicSharedMemorySize, DELTA_SMEM);
    cudaFuncSetAttribute(k_gemm<5>, cudaFuncAttributeMaxDynamicSharedMemorySize, DELTA_SMEM);
    cudaFuncSetAttribute(k_gemm<6>, cudaFuncAttributeMaxDynamicSharedMemorySize, DELTA_SMEM);

    dim3 ggrid(DD / BNT, BD / BMT);  // (32, 4) = 128 CTAs

    k_splitW<<<WV / EW_BLK, EW_BLK>>>(W);
    k_init<<<EW_GRID, EW_BLK>>>(x0);
    k_g1_full<<<ggrid, 512, FULL_SMEM>>>(bias);    // once: stage 1 of step 0

    // step 0: stage 1 already done by k_g1_full
    k_gemm<2><<<ggrid, 512, DELTA_SMEM>>>(bias);
    k_gemm<3><<<ggrid, 512, DELTA_SMEM>>>(bias);
    k_gemm<4><<<ggrid, 512, DELTA_SMEM>>>(bias);
    k_gemm<5><<<ggrid, 512, DELTA_SMEM>>>(bias);
    k_gemm<6><<<ggrid, 512, DELTA_SMEM>>>(bias);

    for (int step = 1; step < MAX_STEPS; step++) {
        k_gemm<1><<<ggrid, 512, DELTA_SMEM>>>(bias);
        k_gemm<2><<<ggrid, 512, DELTA_SMEM>>>(bias);
        k_gemm<3><<<ggrid, 512, DELTA_SMEM>>>(bias);
        k_gemm<4><<<ggrid, 512, DELTA_SMEM>>>(bias);
        k_gemm<5><<<ggrid, 512, DELTA_SMEM>>>(bias);
        k_gemm<6><<<ggrid, 512, DELTA_SMEM>>>(bias);   // fused combine + decide
    }

    k_final<<<EW_GRID, EW_BLK>>>(out);
}